// round 1
// baseline (speedup 1.0000x reference)
#include <cuda_runtime.h>

#define W_g 200
#define H_g 200
#define NQ 40000
#define Dm 256

// Scratch (no allocations allowed)
__device__ float g_v[NQ * Dm];      // value @ W_v + b_v   (40000 x 256)
__device__ float g_soaw[NQ * 192];  // cols 0..127 = so, 128..191 = aw (pre-softmax)
__device__ float g_mid[NQ * Dm];    // deform-attn output  (40000 x 256)

// ---------------------------------------------------------------------------
// SGEMM: C[m, c0+n] = A' @ B + bias, A' is either A (M x K) or the virtual
// concat [A | A+A2] (M x 512 with physical row stride 256).
// Tile: BM=64, BN=64, BK=16, 128 threads, 8x4 per thread.
// Requires M % 64 == 0, N tile-covered by grid, K % 16 == 0 (all true here).
// ---------------------------------------------------------------------------
template <bool CONCAT>
__global__ __launch_bounds__(128) void sgemm_kernel(
    const float* __restrict__ A, const float* __restrict__ A2,
    const float* __restrict__ B, const float* __restrict__ bias,
    float* __restrict__ C, int N, int K, int ldC, int c0)
{
    __shared__ float As[16][68];   // As[k][m], padded for float4 alignment
    __shared__ float Bs[16][64];   // Bs[k][n]

    const int tid = threadIdx.x;
    const int bm  = blockIdx.y * 64;
    const int bn  = blockIdx.x * 64;
    const int tx  = tid & 15;      // col group (16 * 4 = 64)
    const int ty  = tid >> 4;      // row group (8  * 8 = 64)

    const int arow = tid >> 2;            // 0..31
    const int acol = (tid & 3) << 2;      // 0,4,8,12
    const int brow = tid >> 4;            // 0..7
    const int bcol = (tid & 15) << 2;     // 0..60

    float acc[8][4];
    #pragma unroll
    for (int i = 0; i < 8; ++i)
        #pragma unroll
        for (int j = 0; j < 4; ++j) acc[i][j] = 0.f;

    const int ntiles = K >> 4;
    for (int t = 0; t < ntiles; ++t) {
        const int k0 = t << 4;
        // ---- load A tile (transposed into As[k][m]) ----
        #pragma unroll
        for (int r = 0; r < 2; ++r) {
            const int row = bm + arow + r * 32;
            float4 av;
            if (!CONCAT) {
                av = *reinterpret_cast<const float4*>(&A[(size_t)row * K + k0 + acol]);
            } else {
                if (k0 < 256) {
                    av = *reinterpret_cast<const float4*>(&A[(size_t)row * 256 + k0 + acol]);
                } else {
                    float4 a1 = *reinterpret_cast<const float4*>(&A [(size_t)row * 256 + (k0 - 256) + acol]);
                    float4 a2 = *reinterpret_cast<const float4*>(&A2[(size_t)row * 256 + (k0 - 256) + acol]);
                    av = make_float4(a1.x + a2.x, a1.y + a2.y, a1.z + a2.z, a1.w + a2.w);
                }
            }
            As[acol + 0][arow + r * 32] = av.x;
            As[acol + 1][arow + r * 32] = av.y;
            As[acol + 2][arow + r * 32] = av.z;
            As[acol + 3][arow + r * 32] = av.w;
        }
        // ---- load B tile ----
        #pragma unroll
        for (int r = 0; r < 2; ++r) {
            const int row = k0 + brow + r * 8;
            *reinterpret_cast<float4*>(&Bs[brow + r * 8][bcol]) =
                *reinterpret_cast<const float4*>(&B[(size_t)row * N + bn + bcol]);
        }
        __syncthreads();

        #pragma unroll
        for (int k = 0; k < 16; ++k) {
            float4 av1 = *reinterpret_cast<const float4*>(&As[k][ty * 8]);
            float4 av2 = *reinterpret_cast<const float4*>(&As[k][ty * 8 + 4]);
            float4 bv  = *reinterpret_cast<const float4*>(&Bs[k][tx * 4]);
            float a[8] = {av1.x, av1.y, av1.z, av1.w, av2.x, av2.y, av2.z, av2.w};
            float b[4] = {bv.x, bv.y, bv.z, bv.w};
            #pragma unroll
            for (int i = 0; i < 8; ++i)
                #pragma unroll
                for (int j = 0; j < 4; ++j)
                    acc[i][j] = fmaf(a[i], b[j], acc[i][j]);
        }
        __syncthreads();
    }

    // ---- epilogue: bias + store ----
    float bb[4];
    #pragma unroll
    for (int j = 0; j < 4; ++j) bb[j] = bias[bn + tx * 4 + j];
    #pragma unroll
    for (int i = 0; i < 8; ++i) {
        float4 o = make_float4(acc[i][0] + bb[0], acc[i][1] + bb[1],
                               acc[i][2] + bb[2], acc[i][3] + bb[3]);
        *reinterpret_cast<float4*>(
            &C[(size_t)(bm + ty * 8 + i) * ldC + c0 + bn + tx * 4]) = o;
    }
}

// ---------------------------------------------------------------------------
// Deformable sampling: one warp per (query, head); lane = channel (DH=32).
// soaw row layout per q (192 floats):
//   so: col = h*16 + queue*8 + p*2 + xy     (cols 0..127)
//   aw: col = 128 + h*8 + queue*4 + p       (cols 128..191, pre-softmax)
// out_mid[q, h*32+lane] = 0.5 * sum_{queue} sum_p softmax(aw)_p * bilin(v, loc)
// ---------------------------------------------------------------------------
__global__ __launch_bounds__(256) void deform_kernel(
    const float* __restrict__ v, const float* __restrict__ soaw,
    const float* __restrict__ ref, float* __restrict__ outm)
{
    const int q    = blockIdx.x;
    const int h    = threadIdx.x >> 5;
    const int lane = threadIdx.x & 31;

    const float rpx = ref[q * 2 + 0];
    const float rpy = ref[q * 2 + 1];

    const float* srow = soaw + (size_t)q * 192;
    float myv = 0.f;
    if (lane < 16)       myv = srow[h * 16 + lane];
    else if (lane < 24)  myv = srow[128 + h * 8 + (lane - 16)];

    const float* vh = v + h * 32 + lane;
    float acc = 0.f;

    #pragma unroll
    for (int qq = 0; qq < 2; ++qq) {
        // softmax over the 4 points of this queue (broadcast identical in warp)
        float a0 = __shfl_sync(0xffffffffu, myv, 16 + qq * 4 + 0);
        float a1 = __shfl_sync(0xffffffffu, myv, 16 + qq * 4 + 1);
        float a2 = __shfl_sync(0xffffffffu, myv, 16 + qq * 4 + 2);
        float a3 = __shfl_sync(0xffffffffu, myv, 16 + qq * 4 + 3);
        float mx = fmaxf(fmaxf(a0, a1), fmaxf(a2, a3));
        float e0 = expf(a0 - mx), e1 = expf(a1 - mx);
        float e2 = expf(a2 - mx), e3 = expf(a3 - mx);
        float inv = 1.f / (e0 + e1 + e2 + e3);
        float wts[4] = {e0 * inv, e1 * inv, e2 * inv, e3 * inv};

        #pragma unroll
        for (int p = 0; p < 4; ++p) {
            float sx = __shfl_sync(0xffffffffu, myv, qq * 8 + p * 2 + 0);
            float sy = __shfl_sync(0xffffffffu, myv, qq * 8 + p * 2 + 1);
            float x = (rpx + sx / (float)W_g) * (float)W_g - 0.5f;
            float y = (rpy + sy / (float)H_g) * (float)H_g - 0.5f;
            float x0f = floorf(x), y0f = floorf(y);
            int   x0 = (int)x0f,  y0 = (int)y0f;
            float wx1 = x - x0f, wx0 = 1.f - wx1;
            float wy1 = y - y0f, wy0 = 1.f - wy1;

            bool vx0 = (x0 >= 0)     && (x0 < W_g);
            bool vx1 = (x0 + 1 >= 0) && (x0 + 1 < W_g);
            bool vy0 = (y0 >= 0)     && (y0 < H_g);
            bool vy1 = (y0 + 1 >= 0) && (y0 + 1 < H_g);
            int cx0 = min(max(x0, 0),     W_g - 1);
            int cx1 = min(max(x0 + 1, 0), W_g - 1);
            int cy0 = min(max(y0, 0),     H_g - 1);
            int cy1 = min(max(y0 + 1, 0), H_g - 1);

            float s = 0.f, c;
            c = wx0 * wy0; if (vx0 && vy0 && c != 0.f) s += c * vh[((size_t)cy0 * W_g + cx0) * Dm];
            c = wx1 * wy0; if (vx1 && vy0 && c != 0.f) s += c * vh[((size_t)cy0 * W_g + cx1) * Dm];
            c = wx0 * wy1; if (vx0 && vy1 && c != 0.f) s += c * vh[((size_t)cy1 * W_g + cx0) * Dm];
            c = wx1 * wy1; if (vx1 && vy1 && c != 0.f) s += c * vh[((size_t)cy1 * W_g + cx1) * Dm];
            acc += wts[p] * s;
        }
    }

    outm[(size_t)q * Dm + h * 32 + lane] = 0.5f * acc;
}

// ---------------------------------------------------------------------------
extern "C" void kernel_launch(void* const* d_in, const int* in_sizes, int n_in,
                              void* d_out, int out_size)
{
    const float* query     = (const float*)d_in[0];
    const float* query_pos = (const float*)d_in[1];
    const float* refpts    = (const float*)d_in[2];
    const float* W_so      = (const float*)d_in[3];
    const float* b_so      = (const float*)d_in[4];
    const float* W_aw      = (const float*)d_in[5];
    const float* b_aw      = (const float*)d_in[6];
    const float* W_v       = (const float*)d_in[7];
    const float* b_v       = (const float*)d_in[8];
    const float* W_o       = (const float*)d_in[9];
    const float* b_o       = (const float*)d_in[10];
    float* out = (float*)d_out;

    float *gv, *gsoaw, *gmid;
    cudaGetSymbolAddress((void**)&gv,    g_v);
    cudaGetSymbolAddress((void**)&gsoaw, g_soaw);
    cudaGetSymbolAddress((void**)&gmid,  g_mid);

    dim3 blk(128);
    // v = query @ W_v + b_v          (40000 x 256, K=256)
    sgemm_kernel<false><<<dim3(4, NQ / 64), blk>>>(query, nullptr, W_v, b_v, gv, 256, 256, 256, 0);
    // so = [query | query+query_pos] @ W_so + b_so   (N=128, K=512) -> cols 0..127
    sgemm_kernel<true><<<dim3(2, NQ / 64), blk>>>(query, query_pos, W_so, b_so, gsoaw, 128, 512, 192, 0);
    // aw = [query | query+query_pos] @ W_aw + b_aw   (N=64,  K=512) -> cols 128..191
    sgemm_kernel<true><<<dim3(1, NQ / 64), blk>>>(query, query_pos, W_aw, b_aw, gsoaw, 64, 512, 192, 128);
    // deformable attention sampling
    deform_kernel<<<NQ, 256>>>(gv, gsoaw, refpts, gmid);
    // out = mid @ W_o + b_o
    sgemm_kernel<false><<<dim3(4, NQ / 64), blk>>>(gmid, nullptr, W_o, b_o, out, 256, 256, 256, 0);
}

// round 2
// speedup vs baseline: 1.1863x; 1.1863x over previous
#include <cuda_runtime.h>

#define W_g 200
#define H_g 200
#define NQ 40000
#define Dm 256

// Scratch (no allocations allowed)
__device__ float g_v[NQ * Dm];      // value @ W_v + b_v   (40000 x 256)
__device__ float g_soaw[NQ * 192];  // cols 0..127 = so, 128..191 = aw (pre-softmax)
__device__ float g_mid[NQ * Dm];    // deform-attn output  (40000 x 256)

// ---------------------------------------------------------------------------
// SGEMM: C[m, c0+n] = A' @ B + bias, A' is either A (M x K) or the virtual
// concat [A | A+A2] (M x 512 with physical row stride 256).
// Tile: BM=64, BN=64, BK=16, 128 threads, 8x4 per thread.
// ---------------------------------------------------------------------------
template <bool CONCAT>
__global__ __launch_bounds__(128) void sgemm_kernel(
    const float* __restrict__ A, const float* __restrict__ A2,
    const float* __restrict__ B, const float* __restrict__ bias,
    float* __restrict__ C, int N, int K, int ldC, int c0)
{
    __shared__ float As[16][68];   // As[k][m], padded for float4 alignment
    __shared__ float Bs[16][64];   // Bs[k][n]

    const int tid = threadIdx.x;
    const int bm  = blockIdx.y * 64;
    const int bn  = blockIdx.x * 64;
    const int tx  = tid & 15;      // col group (16 * 4 = 64)
    const int ty  = tid >> 4;      // row group (8  * 8 = 64)

    const int arow = tid >> 2;            // 0..31
    const int acol = (tid & 3) << 2;      // 0,4,8,12
    const int brow = tid >> 4;            // 0..7
    const int bcol = (tid & 15) << 2;     // 0..60

    float acc[8][4];
    #pragma unroll
    for (int i = 0; i < 8; ++i)
        #pragma unroll
        for (int j = 0; j < 4; ++j) acc[i][j] = 0.f;

    const int ntiles = K >> 4;
    for (int t = 0; t < ntiles; ++t) {
        const int k0 = t << 4;
        // ---- load A tile (transposed into As[k][m]) ----
        #pragma unroll
        for (int r = 0; r < 2; ++r) {
            const int row = bm + arow + r * 32;
            float4 av;
            if (!CONCAT) {
                av = *reinterpret_cast<const float4*>(&A[(size_t)row * K + k0 + acol]);
            } else {
                if (k0 < 256) {
                    av = *reinterpret_cast<const float4*>(&A[(size_t)row * 256 + k0 + acol]);
                } else {
                    float4 a1 = *reinterpret_cast<const float4*>(&A [(size_t)row * 256 + (k0 - 256) + acol]);
                    float4 a2 = *reinterpret_cast<const float4*>(&A2[(size_t)row * 256 + (k0 - 256) + acol]);
                    av = make_float4(a1.x + a2.x, a1.y + a2.y, a1.z + a2.z, a1.w + a2.w);
                }
            }
            As[acol + 0][arow + r * 32] = av.x;
            As[acol + 1][arow + r * 32] = av.y;
            As[acol + 2][arow + r * 32] = av.z;
            As[acol + 3][arow + r * 32] = av.w;
        }
        // ---- load B tile ----
        #pragma unroll
        for (int r = 0; r < 2; ++r) {
            const int row = k0 + brow + r * 8;
            *reinterpret_cast<float4*>(&Bs[brow + r * 8][bcol]) =
                *reinterpret_cast<const float4*>(&B[(size_t)row * N + bn + bcol]);
        }
        __syncthreads();

        #pragma unroll
        for (int k = 0; k < 16; ++k) {
            float4 av1 = *reinterpret_cast<const float4*>(&As[k][ty * 8]);
            float4 av2 = *reinterpret_cast<const float4*>(&As[k][ty * 8 + 4]);
            float4 bv  = *reinterpret_cast<const float4*>(&Bs[k][tx * 4]);
            float a[8] = {av1.x, av1.y, av1.z, av1.w, av2.x, av2.y, av2.z, av2.w};
            float b[4] = {bv.x, bv.y, bv.z, bv.w};
            #pragma unroll
            for (int i = 0; i < 8; ++i)
                #pragma unroll
                for (int j = 0; j < 4; ++j)
                    acc[i][j] = fmaf(a[i], b[j], acc[i][j]);
        }
        __syncthreads();
    }

    // ---- epilogue: bias + store ----
    float bb[4];
    #pragma unroll
    for (int j = 0; j < 4; ++j) bb[j] = bias[bn + tx * 4 + j];
    #pragma unroll
    for (int i = 0; i < 8; ++i) {
        float4 o = make_float4(acc[i][0] + bb[0], acc[i][1] + bb[1],
                               acc[i][2] + bb[2], acc[i][3] + bb[3]);
        *reinterpret_cast<float4*>(
            &C[(size_t)(bm + ty * 8 + i) * ldC + c0 + bn + tx * 4]) = o;
    }
}

// ---------------------------------------------------------------------------
// Deformable sampling, two-phase.
// Phase 1 (64 threads): thread t = (h, qq, p) computes softmax weight,
//   pre-multiplied bilinear corner weights (x0.5 for queue mean, zeroed if
//   out of bounds) and corner BYTE offsets into v; writes to smem.
// Phase 2 (8 warps): warp = head, lane = channel; 8 points x 4 gathers+FMA.
// ---------------------------------------------------------------------------
__global__ __launch_bounds__(256) void deform_kernel(
    const float* __restrict__ v, const float* __restrict__ soaw,
    const float* __restrict__ ref, float* __restrict__ outm)
{
    __shared__ float4 s_w[64];
    __shared__ int4   s_idx[64];

    const int q   = blockIdx.x;
    const int tid = threadIdx.x;

    if (tid < 64) {
        const int h  = tid >> 3;
        const int qq = (tid >> 2) & 1;
        const int p  = tid & 3;
        const float* srow = soaw + (size_t)q * 192;

        const float rpx = ref[q * 2 + 0];
        const float rpy = ref[q * 2 + 1];

        const float sx = srow[h * 16 + qq * 8 + p * 2 + 0];
        const float sy = srow[h * 16 + qq * 8 + p * 2 + 1];
        float a        = srow[128 + h * 8 + qq * 4 + p];

        // softmax over the aligned group of 4 lanes (same h, qq)
        float m = fmaxf(a, __shfl_xor_sync(0xffffffffu, a, 1));
        m = fmaxf(m, __shfl_xor_sync(0xffffffffu, m, 2));
        float e = __expf(a - m);
        float s = e + __shfl_xor_sync(0xffffffffu, e, 1);
        s = s + __shfl_xor_sync(0xffffffffu, s, 2);
        const float wt = 0.5f * e / s;   // x0.5 = queue mean

        // x = (rpx + sx/W)*W - 0.5 = rpx*W + sx - 0.5
        const float x = fmaf(rpx, (float)W_g, sx) - 0.5f;
        const float y = fmaf(rpy, (float)H_g, sy) - 0.5f;
        const float x0f = floorf(x), y0f = floorf(y);
        const int   x0 = (int)x0f,  y0 = (int)y0f;
        const float wx1 = x - x0f, wx0 = 1.f - wx1;
        const float wy1 = y - y0f, wy0 = 1.f - wy1;

        const bool vx0 = (x0 >= 0) && (x0 < W_g);
        const bool vx1 = (x0 + 1 >= 0) && (x0 + 1 < W_g);
        const bool vy0 = (y0 >= 0) && (y0 < H_g);
        const bool vy1 = (y0 + 1 >= 0) && (y0 + 1 < H_g);
        const int cx0 = min(max(x0, 0),     W_g - 1);
        const int cx1 = min(max(x0 + 1, 0), W_g - 1);
        const int cy0 = min(max(y0, 0),     H_g - 1);
        const int cy1 = min(max(y0 + 1, 0), H_g - 1);

        float4 w;
        w.x = wt * wx0 * wy0 * (float)(vx0 && vy0);
        w.y = wt * wx1 * wy0 * (float)(vx1 && vy0);
        w.z = wt * wx0 * wy1 * (float)(vx0 && vy1);
        w.w = wt * wx1 * wy1 * (float)(vx1 && vy1);

        int4 ix;  // byte offsets into v (row stride Dm floats = 1024 B)
        ix.x = (cy0 * W_g + cx0) * (Dm * 4);
        ix.y = (cy0 * W_g + cx1) * (Dm * 4);
        ix.z = (cy1 * W_g + cx0) * (Dm * 4);
        ix.w = (cy1 * W_g + cx1) * (Dm * 4);

        s_w[tid]   = w;
        s_idx[tid] = ix;
    }
    __syncthreads();

    const int h    = tid >> 5;
    const int lane = tid & 31;
    const char* vh = (const char*)(v + h * 32 + lane);

    float acc = 0.f;
    #pragma unroll
    for (int pp = 0; pp < 8; ++pp) {
        const int t = h * 8 + pp;
        const float4 w  = s_w[t];
        const int4   ix = s_idx[t];
        acc = fmaf(w.x, *(const float*)(vh + ix.x), acc);
        acc = fmaf(w.y, *(const float*)(vh + ix.y), acc);
        acc = fmaf(w.z, *(const float*)(vh + ix.z), acc);
        acc = fmaf(w.w, *(const float*)(vh + ix.w), acc);
    }

    outm[(size_t)q * Dm + h * 32 + lane] = acc;
}

// ---------------------------------------------------------------------------
extern "C" void kernel_launch(void* const* d_in, const int* in_sizes, int n_in,
                              void* d_out, int out_size)
{
    const float* query     = (const float*)d_in[0];
    const float* query_pos = (const float*)d_in[1];
    const float* refpts    = (const float*)d_in[2];
    const float* W_so      = (const float*)d_in[3];
    const float* b_so      = (const float*)d_in[4];
    const float* W_aw      = (const float*)d_in[5];
    const float* b_aw      = (const float*)d_in[6];
    const float* W_v       = (const float*)d_in[7];
    const float* b_v       = (const float*)d_in[8];
    const float* W_o       = (const float*)d_in[9];
    const float* b_o       = (const float*)d_in[10];
    float* out = (float*)d_out;

    float *gv, *gsoaw, *gmid;
    cudaGetSymbolAddress((void**)&gv,    g_v);
    cudaGetSymbolAddress((void**)&gsoaw, g_soaw);
    cudaGetSymbolAddress((void**)&gmid,  g_mid);

    dim3 blk(128);
    // v = query @ W_v + b_v          (40000 x 256, K=256)
    sgemm_kernel<false><<<dim3(4, NQ / 64), blk>>>(query, nullptr, W_v, b_v, gv, 256, 256, 256, 0);
    // so = [query | query+query_pos] @ W_so + b_so   (N=128, K=512) -> cols 0..127
    sgemm_kernel<true><<<dim3(2, NQ / 64), blk>>>(query, query_pos, W_so, b_so, gsoaw, 128, 512, 192, 0);
    // aw = [query | query+query_pos] @ W_aw + b_aw   (N=64,  K=512) -> cols 128..191
    sgemm_kernel<true><<<dim3(1, NQ / 64), blk>>>(query, query_pos, W_aw, b_aw, gsoaw, 64, 512, 192, 128);
    // deformable attention sampling
    deform_kernel<<<NQ, 256>>>(gv, gsoaw, refpts, gmid);
    // out = mid @ W_o + b_o
    sgemm_kernel<false><<<dim3(4, NQ / 64), blk>>>(gmid, nullptr, W_o, b_o, out, 256, 256, 256, 0);
}

// round 3
// speedup vs baseline: 1.3529x; 1.1405x over previous
#include <cuda_runtime.h>

#define W_g 200
#define H_g 200
#define NQ 40000
#define Dm 256

// Scratch (no allocations allowed)
__device__ float g_v[NQ * Dm];      // value @ W_v + b_v   (40000 x 256)
__device__ float g_soaw[NQ * 192];  // cols 0..127 = so, 128..191 = aw (pre-softmax)
__device__ float g_mid[NQ * Dm];    // deform-attn output  (40000 x 256)

// ---------------------------------------------------------------------------
// Double-buffered SGEMM.
// C[m, c0+bn+n] = A' @ B + bias.  A' = A (MxK) or virtual [A | A+A2] (K=512,
// physical row stride 256). Two B/bias sets: blocks with bx < split use set 0
// (bn = bx*64, c0 = 0), others set 1 (bn = (bx-split)*64, c0 = c0_1).
// Tile: BM=64, BN=64, BK=16, 128 threads, 8x4 microtile.
// ---------------------------------------------------------------------------
template <bool CONCAT>
__global__ __launch_bounds__(128) void sgemm_db(
    const float* __restrict__ A, const float* __restrict__ A2,
    const float* __restrict__ B0, const float* __restrict__ bias0, int N0,
    const float* __restrict__ B1, const float* __restrict__ bias1, int N1,
    int split, float* __restrict__ C, int K, int ldC, int c0_1)
{
    __shared__ float As[2][16][68];
    __shared__ float Bs[2][16][64];

    const int tid = threadIdx.x;
    const int bm  = blockIdx.y * 64;
    const int bx  = blockIdx.x;

    const float* B;  const float* bias;  int Nb, bn, c0;
    if (bx < split) { B = B0; bias = bias0; Nb = N0; bn = bx * 64;          c0 = 0;    }
    else            { B = B1; bias = bias1; Nb = N1; bn = (bx - split) * 64; c0 = c0_1; }

    const int tx  = tid & 15;          // col group (16 * 4 = 64)
    const int ty  = tid >> 4;          // row group (8  * 8 = 64)
    const int arow = tid >> 2;         // 0..31
    const int acol = (tid & 3) << 2;   // 0,4,8,12
    const int brow = tid >> 4;         // 0..7
    const int bcol = (tid & 15) << 2;  // 0..60

    float acc[8][4];
    #pragma unroll
    for (int i = 0; i < 8; ++i)
        #pragma unroll
        for (int j = 0; j < 4; ++j) acc[i][j] = 0.f;

    const int ntiles = K >> 4;
    float4 ar0, ar1, br0, br1;

    // ---- tile loader (into registers) ----
    auto ldg_tile = [&](int t) {
        const int k0 = t << 4;
        if (!CONCAT) {
            ar0 = *reinterpret_cast<const float4*>(&A[(size_t)(bm + arow)      * K + k0 + acol]);
            ar1 = *reinterpret_cast<const float4*>(&A[(size_t)(bm + arow + 32) * K + k0 + acol]);
        } else {
            if (k0 < 256) {
                ar0 = *reinterpret_cast<const float4*>(&A[(size_t)(bm + arow)      * 256 + k0 + acol]);
                ar1 = *reinterpret_cast<const float4*>(&A[(size_t)(bm + arow + 32) * 256 + k0 + acol]);
            } else {
                const int kk = k0 - 256;
                float4 p0 = *reinterpret_cast<const float4*>(&A [(size_t)(bm + arow)      * 256 + kk + acol]);
                float4 q0 = *reinterpret_cast<const float4*>(&A2[(size_t)(bm + arow)      * 256 + kk + acol]);
                float4 p1 = *reinterpret_cast<const float4*>(&A [(size_t)(bm + arow + 32) * 256 + kk + acol]);
                float4 q1 = *reinterpret_cast<const float4*>(&A2[(size_t)(bm + arow + 32) * 256 + kk + acol]);
                ar0 = make_float4(p0.x + q0.x, p0.y + q0.y, p0.z + q0.z, p0.w + q0.w);
                ar1 = make_float4(p1.x + q1.x, p1.y + q1.y, p1.z + q1.z, p1.w + q1.w);
            }
        }
        br0 = *reinterpret_cast<const float4*>(&B[(size_t)(k0 + brow)     * Nb + bn + bcol]);
        br1 = *reinterpret_cast<const float4*>(&B[(size_t)(k0 + brow + 8) * Nb + bn + bcol]);
    };

    auto sts_tile = [&](int buf) {
        As[buf][acol + 0][arow] = ar0.x;
        As[buf][acol + 1][arow] = ar0.y;
        As[buf][acol + 2][arow] = ar0.z;
        As[buf][acol + 3][arow] = ar0.w;
        As[buf][acol + 0][arow + 32] = ar1.x;
        As[buf][acol + 1][arow + 32] = ar1.y;
        As[buf][acol + 2][arow + 32] = ar1.z;
        As[buf][acol + 3][arow + 32] = ar1.w;
        *reinterpret_cast<float4*>(&Bs[buf][brow][bcol])     = br0;
        *reinterpret_cast<float4*>(&Bs[buf][brow + 8][bcol]) = br1;
    };

    // ---- prologue ----
    ldg_tile(0);
    sts_tile(0);
    __syncthreads();

    for (int t = 0; t < ntiles; ++t) {
        const int cur = t & 1;
        if (t + 1 < ntiles) ldg_tile(t + 1);

        #pragma unroll
        for (int k = 0; k < 16; ++k) {
            float4 av1 = *reinterpret_cast<const float4*>(&As[cur][k][ty * 8]);
            float4 av2 = *reinterpret_cast<const float4*>(&As[cur][k][ty * 8 + 4]);
            float4 bv  = *reinterpret_cast<const float4*>(&Bs[cur][k][tx * 4]);
            float a[8] = {av1.x, av1.y, av1.z, av1.w, av2.x, av2.y, av2.z, av2.w};
            float b[4] = {bv.x, bv.y, bv.z, bv.w};
            #pragma unroll
            for (int i = 0; i < 8; ++i)
                #pragma unroll
                for (int j = 0; j < 4; ++j)
                    acc[i][j] = fmaf(a[i], b[j], acc[i][j]);
        }

        if (t + 1 < ntiles) {
            sts_tile(1 - cur);
            __syncthreads();
        }
    }

    // ---- epilogue: bias + store ----
    float bb[4];
    #pragma unroll
    for (int j = 0; j < 4; ++j) bb[j] = bias[bn + tx * 4 + j];
    #pragma unroll
    for (int i = 0; i < 8; ++i) {
        float4 o = make_float4(acc[i][0] + bb[0], acc[i][1] + bb[1],
                               acc[i][2] + bb[2], acc[i][3] + bb[3]);
        *reinterpret_cast<float4*>(
            &C[(size_t)(bm + ty * 8 + i) * ldC + c0 + bn + tx * 4]) = o;
    }
}

// ---------------------------------------------------------------------------
// Deformable sampling, two-phase (unchanged from R2).
// ---------------------------------------------------------------------------
__global__ __launch_bounds__(256) void deform_kernel(
    const float* __restrict__ v, const float* __restrict__ soaw,
    const float* __restrict__ ref, float* __restrict__ outm)
{
    __shared__ float4 s_w[64];
    __shared__ int4   s_idx[64];

    const int q   = blockIdx.x;
    const int tid = threadIdx.x;

    if (tid < 64) {
        const int h  = tid >> 3;
        const int qq = (tid >> 2) & 1;
        const int p  = tid & 3;
        const float* srow = soaw + (size_t)q * 192;

        const float rpx = ref[q * 2 + 0];
        const float rpy = ref[q * 2 + 1];

        const float sx = srow[h * 16 + qq * 8 + p * 2 + 0];
        const float sy = srow[h * 16 + qq * 8 + p * 2 + 1];
        float a        = srow[128 + h * 8 + qq * 4 + p];

        float m = fmaxf(a, __shfl_xor_sync(0xffffffffu, a, 1));
        m = fmaxf(m, __shfl_xor_sync(0xffffffffu, m, 2));
        float e = __expf(a - m);
        float s = e + __shfl_xor_sync(0xffffffffu, e, 1);
        s = s + __shfl_xor_sync(0xffffffffu, s, 2);
        const float wt = 0.5f * e / s;

        const float x = fmaf(rpx, (float)W_g, sx) - 0.5f;
        const float y = fmaf(rpy, (float)H_g, sy) - 0.5f;
        const float x0f = floorf(x), y0f = floorf(y);
        const int   x0 = (int)x0f,  y0 = (int)y0f;
        const float wx1 = x - x0f, wx0 = 1.f - wx1;
        const float wy1 = y - y0f, wy0 = 1.f - wy1;

        const bool vx0 = (x0 >= 0) && (x0 < W_g);
        const bool vx1 = (x0 + 1 >= 0) && (x0 + 1 < W_g);
        const bool vy0 = (y0 >= 0) && (y0 < H_g);
        const bool vy1 = (y0 + 1 >= 0) && (y0 + 1 < H_g);
        const int cx0 = min(max(x0, 0),     W_g - 1);
        const int cx1 = min(max(x0 + 1, 0), W_g - 1);
        const int cy0 = min(max(y0, 0),     H_g - 1);
        const int cy1 = min(max(y0 + 1, 0), H_g - 1);

        float4 w;
        w.x = wt * wx0 * wy0 * (float)(vx0 && vy0);
        w.y = wt * wx1 * wy0 * (float)(vx1 && vy0);
        w.z = wt * wx0 * wy1 * (float)(vx0 && vy1);
        w.w = wt * wx1 * wy1 * (float)(vx1 && vy1);

        int4 ix;
        ix.x = (cy0 * W_g + cx0) * (Dm * 4);
        ix.y = (cy0 * W_g + cx1) * (Dm * 4);
        ix.z = (cy1 * W_g + cx0) * (Dm * 4);
        ix.w = (cy1 * W_g + cx1) * (Dm * 4);

        s_w[tid]   = w;
        s_idx[tid] = ix;
    }
    __syncthreads();

    const int h    = tid >> 5;
    const int lane = tid & 31;
    const char* vh = (const char*)(v + h * 32 + lane);

    float acc = 0.f;
    #pragma unroll
    for (int pp = 0; pp < 8; ++pp) {
        const int t = h * 8 + pp;
        const float4 w  = s_w[t];
        const int4   ix = s_idx[t];
        acc = fmaf(w.x, *(const float*)(vh + ix.x), acc);
        acc = fmaf(w.y, *(const float*)(vh + ix.y), acc);
        acc = fmaf(w.z, *(const float*)(vh + ix.z), acc);
        acc = fmaf(w.w, *(const float*)(vh + ix.w), acc);
    }

    outm[(size_t)q * Dm + h * 32 + lane] = acc;
}

// ---------------------------------------------------------------------------
extern "C" void kernel_launch(void* const* d_in, const int* in_sizes, int n_in,
                              void* d_out, int out_size)
{
    const float* query     = (const float*)d_in[0];
    const float* query_pos = (const float*)d_in[1];
    const float* refpts    = (const float*)d_in[2];
    const float* W_so      = (const float*)d_in[3];
    const float* b_so      = (const float*)d_in[4];
    const float* W_aw      = (const float*)d_in[5];
    const float* b_aw      = (const float*)d_in[6];
    const float* W_v       = (const float*)d_in[7];
    const float* b_v       = (const float*)d_in[8];
    const float* W_o       = (const float*)d_in[9];
    const float* b_o       = (const float*)d_in[10];
    float* out = (float*)d_out;

    float *gv, *gsoaw, *gmid;
    cudaGetSymbolAddress((void**)&gv,    g_v);
    cudaGetSymbolAddress((void**)&gsoaw, g_soaw);
    cudaGetSymbolAddress((void**)&gmid,  g_mid);

    dim3 blk(128);
    // v = query @ W_v + b_v          (40000 x 256, K=256)
    sgemm_db<false><<<dim3(4, NQ / 64), blk>>>(
        query, nullptr, W_v, b_v, 256, W_v, b_v, 256, 4, gv, 256, 256, 0);
    // fused: so (N=128, tiles 0-1) + aw (N=64, tile 2), K=512, out cols 0..191
    sgemm_db<true><<<dim3(3, NQ / 64), blk>>>(
        query, query_pos, W_so, b_so, 128, W_aw, b_aw, 64, 2, gsoaw, 512, 192, 128);
    // deformable attention sampling
    deform_kernel<<<NQ, 256>>>(gv, gsoaw, refpts, gmid);
    // out = mid @ W_o + b_o
    sgemm_db<false><<<dim3(4, NQ / 64), blk>>>(
        gmid, nullptr, W_o, b_o, 256, W_o, b_o, 256, 4, out, 256, 256, 0);
}